// round 3
// baseline (speedup 1.0000x reference)
#include <cuda_runtime.h>
#include <math.h>

#define MAX_N 100000
#define F1 128
#define F2 40

// ---------------- scratch (device globals; no allocs allowed) ----------------
__device__ float g_xw[(size_t)MAX_N * F1];   // layer1 GEMM raw output
__device__ float g_h [(size_t)MAX_N * F1];   // layer1 aggregated (pre-relu)
__device__ float g_hw[(size_t)MAX_N * F2];   // layer2 GEMM raw output
__device__ float g_dinv[MAX_N];
__device__ unsigned int g_deg[MAX_N];
__device__ int g_is64;

// ---------------- index dtype handling ----------------
__device__ __forceinline__ int load_idx(const void* p, long long i, int is64) {
    if (is64) return (int)((const long long*)p)[i];
    return ((const int*)p)[i];
}

// Detect int64 vs int32 edge_index: if int64, every odd 32-bit word (high half)
// is zero. Random int32 values in [0,1e5) can't all be zero at 256 sample points.
__global__ void detect_kernel(const void* idx) {
    int t = threadIdx.x;
    int w = ((const int*)idx)[2 * t + 1];
    int bad = __syncthreads_count(w != 0);
    if (t == 0) g_is64 = (bad == 0) ? 1 : 0;
}

// ---------------- degree / dinv ----------------
__global__ void zero_deg_kernel(int M) {
    int i = blockIdx.x * blockDim.x + threadIdx.x;
    if (i < M) g_deg[i] = 0u;
}

__global__ void deg_kernel(const void* idx, int E) {
    int e = blockIdx.x * blockDim.x + threadIdx.x;
    if (e >= E) return;
    int is64 = g_is64;
    int dst = load_idx(idx, (long long)E + e, is64);
    atomicAdd(&g_deg[dst], 1u);
}

__global__ void dinv_kernel(int M) {
    int i = blockIdx.x * blockDim.x + threadIdx.x;
    if (i < M) g_dinv[i] = rsqrtf((float)(g_deg[i] + 1u));  // +1 self-loop
}

// ---------------- GEMM: Y = X(MxK=128) @ W(128xNOUT), fused self-loop init ----
// BM=64 rows per block, 256 threads. W staged in smem in two K=64 chunks
// (keeps static smem <= 32KB). Epilogue writes both Yraw (for edge gather)
// and Yagg = Yraw*dinv[r]^2 + bias (self-loop term + bias as the accumulator
// initialization for the edge scatter).
template<int BN, int NOUT, bool RELU, int LAYER>
__global__ __launch_bounds__(256) void gemm_kernel(
    const float* __restrict__ Xin, const float* __restrict__ W,
    const float* __restrict__ bias, float* __restrict__ Yagg_param, int M)
{
    constexpr int TC  = BN / 4;      // threads covering columns (float4 each)
    constexpr int TR  = 256 / TC;    // thread rows
    constexpr int RPT = 64 / TR;     // rows per thread

    __shared__ float Ws[64][BN];

    const float* X    = (LAYER == 1) ? Xin  : g_h;
    float*       Yraw = (LAYER == 1) ? g_xw : g_hw;
    float*       Yagg = (LAYER == 1) ? g_h  : Yagg_param;

    int tid = threadIdx.x;
    int tx = tid % TC, ty = tid / TC;
    int c0 = tx * 4;
    int rowBase = blockIdx.x * 64 + ty * RPT;

    float acc[RPT][4];
#pragma unroll
    for (int i = 0; i < RPT; i++)
#pragma unroll
        for (int c = 0; c < 4; c++) acc[i][c] = 0.f;

    for (int k0 = 0; k0 < 128; k0 += 64) {
        // stage W chunk (zero-pad columns >= NOUT)
        for (int i = tid; i < 64 * BN; i += 256) {
            int kk = i / BN, c = i % BN;
            Ws[kk][c] = (c < NOUT) ? W[(k0 + kk) * NOUT + c] : 0.f;
        }
        __syncthreads();

#pragma unroll
        for (int kk = 0; kk < 64; kk += 4) {
            float4 wv[4];
#pragma unroll
            for (int j = 0; j < 4; j++)
                wv[j] = *(const float4*)&Ws[kk + j][c0];
#pragma unroll
            for (int i = 0; i < RPT; i++) {
                int r = rowBase + i; if (r >= M) r = M - 1;
                float4 xv = *(const float4*)&X[(size_t)r * 128 + k0 + kk];
                if (RELU) {
                    xv.x = fmaxf(xv.x, 0.f); xv.y = fmaxf(xv.y, 0.f);
                    xv.z = fmaxf(xv.z, 0.f); xv.w = fmaxf(xv.w, 0.f);
                }
#pragma unroll
                for (int j = 0; j < 4; j++) {
                    float xj = (&xv.x)[j];
                    acc[i][0] = fmaf(xj, (&wv[j].x)[0], acc[i][0]);
                    acc[i][1] = fmaf(xj, (&wv[j].x)[1], acc[i][1]);
                    acc[i][2] = fmaf(xj, (&wv[j].x)[2], acc[i][2]);
                    acc[i][3] = fmaf(xj, (&wv[j].x)[3], acc[i][3]);
                }
            }
        }
        __syncthreads();
    }

    if (c0 < NOUT) {
        float b0 = bias[c0 + 0], b1v = bias[c0 + 1], b2v = bias[c0 + 2], b3v = bias[c0 + 3];
#pragma unroll
        for (int i = 0; i < RPT; i++) {
            int r = rowBase + i;
            if (r < M) {
                float dv = g_dinv[r];
                float d2 = dv * dv;
                float4 o = make_float4(acc[i][0], acc[i][1], acc[i][2], acc[i][3]);
                *(float4*)&Yraw[(size_t)r * NOUT + c0] = o;
                float4 a;
                a.x = fmaf(o.x, d2, b0); a.y = fmaf(o.y, d2, b1v);
                a.z = fmaf(o.z, d2, b2v); a.w = fmaf(o.w, d2, b3v);
                *(float4*)&Yagg[(size_t)r * NOUT + c0] = a;
            }
        }
    }
}

// ---------------- edge scatter: warp per edge ----------------
__device__ __forceinline__ void red_add_f32x4(float* p, float4 v) {
    asm volatile("red.global.add.v4.f32 [%0], {%1,%2,%3,%4};"
                 :: "l"(p), "f"(v.x), "f"(v.y), "f"(v.z), "f"(v.w) : "memory");
}

__global__ __launch_bounds__(256) void scatter128_kernel(const void* idx, int E) {
    int gw = (blockIdx.x * blockDim.x + threadIdx.x) >> 5;
    int lane = threadIdx.x & 31;
    if (gw >= E) return;
    int is64 = g_is64;
    int src = load_idx(idx, gw, is64);
    int dst = load_idx(idx, (long long)E + gw, is64);
    float w = g_dinv[src] * g_dinv[dst];
    float4 v = *((const float4*)(g_xw + (size_t)src * 128) + lane);
    v.x *= w; v.y *= w; v.z *= w; v.w *= w;
    red_add_f32x4(g_h + (size_t)dst * 128 + lane * 4, v);
}

__global__ __launch_bounds__(256) void scatter40_kernel(const void* idx, int E,
                                                        float* __restrict__ out) {
    int gw = (blockIdx.x * blockDim.x + threadIdx.x) >> 5;
    int lane = threadIdx.x & 31;
    if (gw >= E) return;
    int is64 = g_is64;
    int src = load_idx(idx, gw, is64);
    int dst = load_idx(idx, (long long)E + gw, is64);
    float w = g_dinv[src] * g_dinv[dst];
    if (lane < 10) {
        float4 v = *((const float4*)(g_hw + (size_t)src * 40) + lane);
        v.x *= w; v.y *= w; v.z *= w; v.w *= w;
        red_add_f32x4(out + (size_t)dst * 40 + lane * 4, v);
    }
}

// ---------------- log_softmax over 40 classes, warp per row, in place -------
__global__ __launch_bounds__(256) void logsoftmax_kernel(float* __restrict__ out, int M) {
    int r = (blockIdx.x * blockDim.x + threadIdx.x) >> 5;
    int lane = threadIdx.x & 31;
    if (r >= M) return;
    float* row = out + (size_t)r * 40;
    float a = row[lane];
    float b = (lane < 8) ? row[32 + lane] : -INFINITY;
    float m = fmaxf(a, b);
#pragma unroll
    for (int o = 16; o; o >>= 1) m = fmaxf(m, __shfl_xor_sync(0xFFFFFFFFu, m, o));
    float s = __expf(a - m) + ((lane < 8) ? __expf(b - m) : 0.f);
#pragma unroll
    for (int o = 16; o; o >>= 1) s += __shfl_xor_sync(0xFFFFFFFFu, s, o);
    float L = m + __logf(s);
    row[lane] = a - L;
    if (lane < 8) row[32 + lane] = b - L;
}

// ---------------- launch ----------------
extern "C" void kernel_launch(void* const* d_in, const int* in_sizes, int n_in,
                              void* d_out, int out_size) {
    const float* x  = (const float*)d_in[0];
    const void*  ei = d_in[1];
    const float* W1 = (const float*)d_in[2];
    const float* b1 = (const float*)d_in[3];
    const float* W2 = (const float*)d_in[4];
    const float* b2 = (const float*)d_in[5];
    float* out = (float*)d_out;

    int M = in_sizes[0] / F1;       // 100000
    int E = in_sizes[1] / 2;        // 640000 (element count is dtype-invariant)

    detect_kernel<<<1, 256>>>(ei);
    zero_deg_kernel<<<(M + 255) / 256, 256>>>(M);
    deg_kernel<<<(E + 255) / 256, 256>>>(ei, E);
    dinv_kernel<<<(M + 255) / 256, 256>>>(M);

    // layer 1: g_xw = x@W1 ; g_h = g_xw*dinv^2 + b1
    gemm_kernel<128, 128, false, 1><<<(M + 63) / 64, 256>>>(x, W1, b1, nullptr, M);
    // edge aggregation into g_h
    scatter128_kernel<<<(E * 32 + 255) / 256, 256>>>(ei, E);

    // layer 2: g_hw = relu(g_h)@W2 ; out = g_hw*dinv^2 + b2   (BN padded 40->64)
    gemm_kernel<64, 40, true, 2><<<(M + 63) / 64, 256>>>(nullptr, W2, b2, out, M);
    // edge aggregation into out
    scatter40_kernel<<<(E * 32 + 255) / 256, 256>>>(ei, E, out);

    logsoftmax_kernel<<<(M * 32 + 255) / 256, 256>>>(out, M);
}

// round 11
// speedup vs baseline: 1.1094x; 1.1094x over previous
#include <cuda_runtime.h>
#include <cuda_bf16.h>
#include <math.h>
#include <stdint.h>

#define MAX_N 100000
#define F1 128
#define F2 40

// ---------------- scratch (device globals; no allocs allowed) ----------------
__device__ float g_xw[(size_t)MAX_N * F1];   // layer1 output, pre-scaled by dinv[row]
__device__ float g_h [(size_t)MAX_N * F1];   // layer1 aggregated (pre-relu)
__device__ float g_hw[(size_t)MAX_N * F2];   // layer2 output, pre-scaled by dinv[row]
__device__ float g_dinv[MAX_N];
__device__ unsigned int g_deg[MAX_N];
__device__ int g_is64;

// Pre-split bf16 W^T images, [n][k] layout, 272-byte row stride (bank-conflict-free).
#define BROW 272
__device__ __align__(16) uint8_t g_B1hi[128 * BROW];
__device__ __align__(16) uint8_t g_B1lo[128 * BROW];
__device__ __align__(16) uint8_t g_B2hi[40 * BROW];
__device__ __align__(16) uint8_t g_B2lo[40 * BROW];

// ---------------- index dtype handling ----------------
__device__ __forceinline__ int load_idx(const void* p, long long i, int is64) {
    if (is64) return (int)((const long long*)p)[i];
    return ((const int*)p)[i];
}

__global__ void detect_kernel(const void* idx) {
    int t = threadIdx.x;
    int w = ((const int*)idx)[2 * t + 1];
    int bad = __syncthreads_count(w != 0);
    if (t == 0) g_is64 = (bad == 0) ? 1 : 0;
}

// ---------------- degree / dinv ----------------
__global__ void zero_deg_kernel(int M) {
    int i = blockIdx.x * blockDim.x + threadIdx.x;
    if (i < M) g_deg[i] = 0u;
}
__global__ void deg_kernel(const void* idx, int E) {
    int e = blockIdx.x * blockDim.x + threadIdx.x;
    if (e >= E) return;
    int dst = load_idx(idx, (long long)E + e, g_is64);
    atomicAdd(&g_deg[dst], 1u);
}
__global__ void dinv_kernel(int M) {
    int i = blockIdx.x * blockDim.x + threadIdx.x;
    if (i < M) g_dinv[i] = rsqrtf((float)(g_deg[i] + 1u));  // +1 self-loop
}

// ---------------- W preprocessing: transpose + hi/lo bf16 split -------------
__global__ void prep_w_kernel(const float* __restrict__ W1, const float* __restrict__ W2) {
    int i = blockIdx.x * blockDim.x + threadIdx.x;
    if (i < 128 * 128) {            // layer1: image row n, col k = W1[k][n]
        int k = i >> 7, n = i & 127;
        float w = W1[k * 128 + n];
        __nv_bfloat16 hi = __float2bfloat16(w);
        __nv_bfloat16 lo = __float2bfloat16(w - __bfloat162float(hi));
        *(__nv_bfloat16*)(g_B1hi + n * BROW + k * 2) = hi;
        *(__nv_bfloat16*)(g_B1lo + n * BROW + k * 2) = lo;
    }
    if (i < 40 * 128) {             // layer2: 40 n-rows
        int k = i / 40, n = i % 40;
        float w = W2[k * F2 + n];
        __nv_bfloat16 hi = __float2bfloat16(w);
        __nv_bfloat16 lo = __float2bfloat16(w - __bfloat162float(hi));
        *(__nv_bfloat16*)(g_B2hi + n * BROW + k * 2) = hi;
        *(__nv_bfloat16*)(g_B2lo + n * BROW + k * 2) = lo;
    }
}

// ---------------- mma.sync bf16 GEMM: 128 rows x NOUT cols x K=128 ----------
// D = Ahi@Bhi + Alo@Bhi + Ahi@Blo (bf16 split, fp32 accumulate).
// Epilogue: Ysc[r][c] = D*dinv[r]; Yagg[r][c] = D*dinv[r]^2 + bias[c].
__device__ __forceinline__ void mma16816(float* d, uint32_t a0, uint32_t a1,
                                         uint32_t a2, uint32_t a3,
                                         uint32_t b0, uint32_t b1) {
    asm volatile(
        "mma.sync.aligned.m16n8k16.row.col.f32.bf16.bf16.f32 "
        "{%0,%1,%2,%3}, {%4,%5,%6,%7}, {%8,%9}, {%0,%1,%2,%3};"
        : "+f"(d[0]), "+f"(d[1]), "+f"(d[2]), "+f"(d[3])
        : "r"(a0), "r"(a1), "r"(a2), "r"(a3), "r"(b0), "r"(b1));
}

template<int NP, int NOUT, bool RELU, int LAYER>
__global__ __launch_bounds__(256, 1) void mma_gemm_kernel(
    const float* __restrict__ Xin, const float* __restrict__ bias_g,
    float* __restrict__ Yagg_param, int M)
{
    constexpr int NT  = NOUT / 8;          // n-tiles (16 or 5)
    constexpr int ASZ = 128 * BROW;
    constexpr int BSZ = NP * BROW;

    extern __shared__ char smem[];
    char* Ahi = smem;
    char* Alo = smem + ASZ;
    char* Bhi = smem + 2 * ASZ;
    char* Blo = smem + 2 * ASZ + BSZ;

    int tid = threadIdx.x, wid = tid >> 5, lane = tid & 31;
    int g = lane >> 2, t4 = lane & 3;
    int rowBase = blockIdx.x * 128;

    const float* X    = (LAYER == 1) ? Xin  : g_h;
    float*       Ysc  = (LAYER == 1) ? g_xw : g_hw;
    float*       Yagg = (LAYER == 1) ? g_h  : Yagg_param;
    const uint4* bh_src = (const uint4*)((LAYER == 1) ? g_B1hi : g_B2hi);
    const uint4* bl_src = (const uint4*)((LAYER == 1) ? g_B1lo : g_B2lo);

    // copy pre-split B images (BSZ multiple of 16: 272*NP)
    for (int i = tid; i < BSZ / 16; i += 256) {
        ((uint4*)Bhi)[i] = bh_src[i];
        ((uint4*)Blo)[i] = bl_src[i];
    }

    // stage A: fp32 -> bf16 hi/lo, [row][k] stride 272B
    for (int idx = tid; idx < 128 * 32; idx += 256) {
        int rl = idx >> 5, k = (idx & 31) * 4;
        int r = rowBase + rl; if (r >= M) r = M - 1;
        float4 xv = *(const float4*)&X[(size_t)r * 128 + k];
        if (RELU) {
            xv.x = fmaxf(xv.x, 0.f); xv.y = fmaxf(xv.y, 0.f);
            xv.z = fmaxf(xv.z, 0.f); xv.w = fmaxf(xv.w, 0.f);
        }
        unsigned short h[4], l[4];
#pragma unroll
        for (int j = 0; j < 4; j++) {
            float v = (&xv.x)[j];
            __nv_bfloat16 hb = __float2bfloat16(v);
            __nv_bfloat16 lb = __float2bfloat16(v - __bfloat162float(hb));
            h[j] = __bfloat16_as_ushort(hb); l[j] = __bfloat16_as_ushort(lb);
        }
        uint2 hp = make_uint2((uint32_t)h[0] | ((uint32_t)h[1] << 16),
                              (uint32_t)h[2] | ((uint32_t)h[3] << 16));
        uint2 lp = make_uint2((uint32_t)l[0] | ((uint32_t)l[1] << 16),
                              (uint32_t)l[2] | ((uint32_t)l[3] << 16));
        *(uint2*)(Ahi + rl * BROW + k * 2) = hp;
        *(uint2*)(Alo + rl * BROW + k * 2) = lp;
    }
    __syncthreads();

    float acc[NT * 4];
#pragma unroll
    for (int i = 0; i < NT * 4; i++) acc[i] = 0.f;

    const char* Arow0 = Ahi + (wid * 16 + g) * BROW;   // pass-dependent below
    const int kofs0 = t4 * 4;                          // (2*t4 bf16) * 2B

#pragma unroll
    for (int p = 0; p < 3; p++) {
        const char* Ab = (p == 1) ? (Arow0 + ASZ) : Arow0;       // Alo on pass 1
        const char* Bb = (p == 2) ? Blo : Bhi;                   // Blo on pass 2
#pragma unroll
        for (int ks = 0; ks < 8; ks++) {
            int kb = ks * 32 + kofs0;
            uint32_t a0 = *(const uint32_t*)(Ab + kb);
            uint32_t a1 = *(const uint32_t*)(Ab + 8 * BROW + kb);
            uint32_t a2 = *(const uint32_t*)(Ab + kb + 16);
            uint32_t a3 = *(const uint32_t*)(Ab + 8 * BROW + kb + 16);
#pragma unroll
            for (int nt = 0; nt < NT; nt++) {
                const char* Bp = Bb + (nt * 8 + g) * BROW + kb;
                uint32_t b0 = *(const uint32_t*)(Bp);
                uint32_t b1 = *(const uint32_t*)(Bp + 16);
                mma16816(acc + nt * 4, a0, a1, a2, a3, b0, b1);
            }
        }
    }

    // epilogue: rows r0 = base + wid*16 + g, r1 = r0 + 8; cols nt*8 + 2*t4 (+1)
    int r0 = rowBase + wid * 16 + g, r1 = r0 + 8;
    float dv0 = (r0 < M) ? g_dinv[r0] : 0.f;
    float dv1 = (r1 < M) ? g_dinv[r1] : 0.f;
    float q0 = dv0 * dv0, q1 = dv1 * dv1;
#pragma unroll
    for (int nt = 0; nt < NT; nt++) {
        int c = nt * 8 + t4 * 2;
        float2 bv = *(const float2*)&bias_g[c];
        if (r0 < M) {
            float2 s = make_float2(acc[nt * 4 + 0] * dv0, acc[nt * 4 + 1] * dv0);
            *(float2*)&Ysc[(size_t)r0 * NOUT + c] = s;
            float2 a = make_float2(fmaf(acc[nt * 4 + 0], q0, bv.x),
                                   fmaf(acc[nt * 4 + 1], q0, bv.y));
            *(float2*)&Yagg[(size_t)r0 * NOUT + c] = a;
        }
        if (r1 < M) {
            float2 s = make_float2(acc[nt * 4 + 2] * dv1, acc[nt * 4 + 3] * dv1);
            *(float2*)&Ysc[(size_t)r1 * NOUT + c] = s;
            float2 a = make_float2(fmaf(acc[nt * 4 + 2], q1, bv.x),
                                   fmaf(acc[nt * 4 + 3], q1, bv.y));
            *(float2*)&Yagg[(size_t)r1 * NOUT + c] = a;
        }
    }
}

// ---------------- edge scatter: warp per edge ----------------
__device__ __forceinline__ void red_add_f32x4(float* p, float4 v) {
    asm volatile("red.global.add.v4.f32 [%0], {%1,%2,%3,%4};"
                 :: "l"(p), "f"(v.x), "f"(v.y), "f"(v.z), "f"(v.w) : "memory");
}

__global__ __launch_bounds__(256) void scatter128_kernel(const void* idx, int E) {
    int gw = (blockIdx.x * blockDim.x + threadIdx.x) >> 5;
    int lane = threadIdx.x & 31;
    if (gw >= E) return;
    int is64 = g_is64;
    int src = load_idx(idx, gw, is64);
    int dst = load_idx(idx, (long long)E + gw, is64);
    float w = g_dinv[dst];                       // src scale folded into g_xw
    float4 v = *((const float4*)(g_xw + (size_t)src * 128) + lane);
    v.x *= w; v.y *= w; v.z *= w; v.w *= w;
    red_add_f32x4(g_h + (size_t)dst * 128 + lane * 4, v);
}

__global__ __launch_bounds__(256) void scatter40_kernel(const void* idx, int E,
                                                        float* __restrict__ out) {
    int gw = (blockIdx.x * blockDim.x + threadIdx.x) >> 5;
    int lane = threadIdx.x & 31;
    if (gw >= E) return;
    int is64 = g_is64;
    int src = load_idx(idx, gw, is64);
    int dst = load_idx(idx, (long long)E + gw, is64);
    float w = g_dinv[dst];
    if (lane < 10) {
        float4 v = *((const float4*)(g_hw + (size_t)src * 40) + lane);
        v.x *= w; v.y *= w; v.z *= w; v.w *= w;
        red_add_f32x4(out + (size_t)dst * 40 + lane * 4, v);
    }
}

// ---------------- log_softmax over 40 classes, warp per row, in place -------
__global__ __launch_bounds__(256) void logsoftmax_kernel(float* __restrict__ out, int M) {
    int r = (blockIdx.x * blockDim.x + threadIdx.x) >> 5;
    int lane = threadIdx.x & 31;
    if (r >= M) return;
    float* row = out + (size_t)r * 40;
    float a = row[lane];
    float b = (lane < 8) ? row[32 + lane] : -INFINITY;
    float m = fmaxf(a, b);
#pragma unroll
    for (int o = 16; o; o >>= 1) m = fmaxf(m, __shfl_xor_sync(0xFFFFFFFFu, m, o));
    float s = __expf(a - m) + ((lane < 8) ? __expf(b - m) : 0.f);
#pragma unroll
    for (int o = 16; o; o >>= 1) s += __shfl_xor_sync(0xFFFFFFFFu, s, o);
    float L = m + __logf(s);
    row[lane] = a - L;
    if (lane < 8) row[32 + lane] = b - L;
}

// ---------------- launch ----------------
extern "C" void kernel_launch(void* const* d_in, const int* in_sizes, int n_in,
                              void* d_out, int out_size) {
    const float* x  = (const float*)d_in[0];
    const void*  ei = d_in[1];
    const float* W1 = (const float*)d_in[2];
    const float* b1 = (const float*)d_in[3];
    const float* W2 = (const float*)d_in[4];
    const float* b2 = (const float*)d_in[5];
    float* out = (float*)d_out;

    int M = in_sizes[0] / F1;       // 100000
    int E = in_sizes[1] / 2;        // 640000

    constexpr int SM1 = 2 * (128 * BROW) + 2 * (128 * BROW);  // 139264
    constexpr int SM2 = 2 * (128 * BROW) + 2 * (40 * BROW);   //  91392
    cudaFuncSetAttribute(mma_gemm_kernel<128, 128, false, 1>,
                         cudaFuncAttributeMaxDynamicSharedMemorySize, SM1);
    cudaFuncSetAttribute(mma_gemm_kernel<40, 40, true, 2>,
                         cudaFuncAttributeMaxDynamicSharedMemorySize, SM2);

    detect_kernel<<<1, 256>>>(ei);
    zero_deg_kernel<<<(M + 255) / 256, 256>>>(M);
    deg_kernel<<<(E + 255) / 256, 256>>>(ei, E);
    dinv_kernel<<<(M + 255) / 256, 256>>>(M);
    prep_w_kernel<<<64, 256>>>(W1, W2);

    int nCTA = (M + 127) / 128;
    // layer 1: g_xw = (x@W1)*dinv ; g_h = (x@W1)*dinv^2 + b1
    mma_gemm_kernel<128, 128, false, 1><<<nCTA, 256, SM1>>>(x, b1, nullptr, M);
    scatter128_kernel<<<(E * 32 + 255) / 256, 256>>>(ei, E);

    // layer 2: g_hw = (relu(g_h)@W2)*dinv ; out = (...)*dinv^2 + b2
    mma_gemm_kernel<40, 40, true, 2><<<nCTA, 256, SM2>>>(nullptr, b2, out, M);
    scatter40_kernel<<<(E * 32 + 255) / 256, 256>>>(ei, E, out);

    logsoftmax_kernel<<<(M * 32 + 255) / 256, 256>>>(out, M);
}

// round 14
// speedup vs baseline: 1.2198x; 1.0995x over previous
#include <cuda_runtime.h>
#include <cuda_bf16.h>
#include <math.h>
#include <stdint.h>

#define MAX_N 100000
#define MAX_E 1048576
#define F1 128
#define F2 40

// ---------------- scratch (device globals; no allocs allowed) ----------------
__device__ float g_xw[(size_t)MAX_N * F1];   // layer1 output, pre-scaled by dinv[row]
__device__ float g_h [(size_t)MAX_N * F1];   // layer1 aggregated (pre-relu)
__device__ float g_hw[(size_t)MAX_N * F2];   // layer2 output, pre-scaled by dinv[row]
__device__ float g_dinv[MAX_N];
__device__ unsigned int g_deg[MAX_N];
__device__ unsigned int g_rs[MAX_N];         // block-local exclusive scan
__device__ unsigned int g_bsum[512];
__device__ unsigned int g_boff[512];
__device__ unsigned int g_row[MAX_N];        // CSR row starts
__device__ unsigned int g_cursor[MAX_N];
__device__ int g_esrc[MAX_E];                // CSR src indices (dst-sorted)
__device__ int g_is64;

// Pre-split bf16 W^T images, [n][k] layout, 272-byte row stride (bank-conflict-free).
#define BROW 272
__device__ __align__(16) uint8_t g_B1hi[128 * BROW];
__device__ __align__(16) uint8_t g_B1lo[128 * BROW];
__device__ __align__(16) uint8_t g_B2hi[40 * BROW];
__device__ __align__(16) uint8_t g_B2lo[40 * BROW];

// ---------------- index dtype handling ----------------
__device__ __forceinline__ int load_idx(const void* p, long long i, int is64) {
    if (is64) return (int)((const long long*)p)[i];
    return ((const int*)p)[i];
}

__global__ void detect_kernel(const void* idx) {
    int t = threadIdx.x;
    int w = ((const int*)idx)[2 * t + 1];
    int bad = __syncthreads_count(w != 0);
    if (t == 0) g_is64 = (bad == 0) ? 1 : 0;
}

// ---------------- degree / dinv ----------------
__global__ void zero_deg_kernel(int M) {
    int i = blockIdx.x * blockDim.x + threadIdx.x;
    if (i < M) g_deg[i] = 0u;
}
__global__ void deg_kernel(const void* idx, int E) {
    int e = blockIdx.x * blockDim.x + threadIdx.x;
    if (e >= E) return;
    int dst = load_idx(idx, (long long)E + e, g_is64);
    atomicAdd(&g_deg[dst], 1u);
}
__global__ void dinv_kernel(int M) {
    int i = blockIdx.x * blockDim.x + threadIdx.x;
    if (i < M) g_dinv[i] = rsqrtf((float)(g_deg[i] + 1u));  // +1 self-loop
}

// ---------------- CSR build: scan + reorder ----------------
__global__ void scan1_kernel(int M) {
    __shared__ unsigned int s[256];
    int i = blockIdx.x * 256 + threadIdx.x;
    unsigned int v = (i < M) ? g_deg[i] : 0u;
    s[threadIdx.x] = v;
    __syncthreads();
    for (int o = 1; o < 256; o <<= 1) {
        unsigned int t = (threadIdx.x >= o) ? s[threadIdx.x - o] : 0u;
        __syncthreads();
        s[threadIdx.x] += t;
        __syncthreads();
    }
    if (i < M) g_rs[i] = s[threadIdx.x] - v;   // exclusive
    if (threadIdx.x == 255) g_bsum[blockIdx.x] = s[255];
}
__global__ void scan2_kernel(int NB) {
    if (threadIdx.x == 0) {
        unsigned int acc = 0;
        for (int b = 0; b < NB; b++) { g_boff[b] = acc; acc += g_bsum[b]; }
    }
}
__global__ void scan3_kernel(int M) {
    int i = blockIdx.x * blockDim.x + threadIdx.x;
    if (i < M) {
        unsigned int r = g_rs[i] + g_boff[i >> 8];
        g_row[i] = r;
        g_cursor[i] = r;
    }
}
__global__ void reorder_kernel(const void* idx, int E) {
    int e = blockIdx.x * blockDim.x + threadIdx.x;
    if (e >= E) return;
    int is64 = g_is64;
    int src = load_idx(idx, e, is64);
    int dst = load_idx(idx, (long long)E + e, is64);
    unsigned int pos = atomicAdd(&g_cursor[dst], 1u);
    g_esrc[pos] = src;
}

// ---------------- W preprocessing: transpose + hi/lo bf16 split -------------
__global__ void prep_w_kernel(const float* __restrict__ W1, const float* __restrict__ W2) {
    int i = blockIdx.x * blockDim.x + threadIdx.x;
    if (i < 128 * 128) {            // layer1: image row n, col k = W1[k][n]
        int k = i >> 7, n = i & 127;
        float w = W1[k * 128 + n];
        __nv_bfloat16 hi = __float2bfloat16(w);
        __nv_bfloat16 lo = __float2bfloat16(w - __bfloat162float(hi));
        *(__nv_bfloat16*)(g_B1hi + n * BROW + k * 2) = hi;
        *(__nv_bfloat16*)(g_B1lo + n * BROW + k * 2) = lo;
    }
    if (i < 40 * 128) {             // layer2: 40 n-rows
        int k = i / 40, n = i % 40;
        float w = W2[k * F2 + n];
        __nv_bfloat16 hi = __float2bfloat16(w);
        __nv_bfloat16 lo = __float2bfloat16(w - __bfloat162float(hi));
        *(__nv_bfloat16*)(g_B2hi + n * BROW + k * 2) = hi;
        *(__nv_bfloat16*)(g_B2lo + n * BROW + k * 2) = lo;
    }
}

// ---------------- mma.sync bf16 GEMM: 128 rows x NOUT cols x K=128 ----------
__device__ __forceinline__ void mma16816(float* d, uint32_t a0, uint32_t a1,
                                         uint32_t a2, uint32_t a3,
                                         uint32_t b0, uint32_t b1) {
    asm volatile(
        "mma.sync.aligned.m16n8k16.row.col.f32.bf16.bf16.f32 "
        "{%0,%1,%2,%3}, {%4,%5,%6,%7}, {%8,%9}, {%0,%1,%2,%3};"
        : "+f"(d[0]), "+f"(d[1]), "+f"(d[2]), "+f"(d[3])
        : "r"(a0), "r"(a1), "r"(a2), "r"(a3), "r"(b0), "r"(b1));
}

template<int NP, int NOUT, bool RELU, int LAYER>
__global__ __launch_bounds__(256, 1) void mma_gemm_kernel(
    const float* __restrict__ Xin, const float* __restrict__ bias_g,
    float* __restrict__ Yagg_param, int M)
{
    constexpr int NT  = NOUT / 8;
    constexpr int ASZ = 128 * BROW;
    constexpr int BSZ = NP * BROW;

    extern __shared__ char smem[];
    char* Ahi = smem;
    char* Alo = smem + ASZ;
    char* Bhi = smem + 2 * ASZ;
    char* Blo = smem + 2 * ASZ + BSZ;

    int tid = threadIdx.x, wid = tid >> 5, lane = tid & 31;
    int g = lane >> 2, t4 = lane & 3;
    int rowBase = blockIdx.x * 128;

    const float* X    = (LAYER == 1) ? Xin  : g_h;
    float*       Ysc  = (LAYER == 1) ? g_xw : g_hw;
    float*       Yagg = (LAYER == 1) ? g_h  : Yagg_param;
    const uint4* bh_src = (const uint4*)((LAYER == 1) ? g_B1hi : g_B2hi);
    const uint4* bl_src = (const uint4*)((LAYER == 1) ? g_B1lo : g_B2lo);

    for (int i = tid; i < BSZ / 16; i += 256) {
        ((uint4*)Bhi)[i] = bh_src[i];
        ((uint4*)Blo)[i] = bl_src[i];
    }

    for (int idx = tid; idx < 128 * 32; idx += 256) {
        int rl = idx >> 5, k = (idx & 31) * 4;
        int r = rowBase + rl; if (r >= M) r = M - 1;
        float4 xv = *(const float4*)&X[(size_t)r * 128 + k];
        if (RELU) {
            xv.x = fmaxf(xv.x, 0.f); xv.y = fmaxf(xv.y, 0.f);
            xv.z = fmaxf(xv.z, 0.f); xv.w = fmaxf(xv.w, 0.f);
        }
        unsigned short h[4], l[4];
#pragma unroll
        for (int j = 0; j < 4; j++) {
            float v = (&xv.x)[j];
            __nv_bfloat16 hb = __float2bfloat16(v);
            __nv_bfloat16 lb = __float2bfloat16(v - __bfloat162float(hb));
            h[j] = __bfloat16_as_ushort(hb); l[j] = __bfloat16_as_ushort(lb);
        }
        uint2 hp = make_uint2((uint32_t)h[0] | ((uint32_t)h[1] << 16),
                              (uint32_t)h[2] | ((uint32_t)h[3] << 16));
        uint2 lp = make_uint2((uint32_t)l[0] | ((uint32_t)l[1] << 16),
                              (uint32_t)l[2] | ((uint32_t)l[3] << 16));
        *(uint2*)(Ahi + rl * BROW + k * 2) = hp;
        *(uint2*)(Alo + rl * BROW + k * 2) = lp;
    }
    __syncthreads();

    float acc[NT * 4];
#pragma unroll
    for (int i = 0; i < NT * 4; i++) acc[i] = 0.f;

    const char* Arow0 = Ahi + (wid * 16 + g) * BROW;
    const int kofs0 = t4 * 4;

#pragma unroll
    for (int p = 0; p < 3; p++) {
        const char* Ab = (p == 1) ? (Arow0 + ASZ) : Arow0;
        const char* Bb = (p == 2) ? Blo : Bhi;
#pragma unroll
        for (int ks = 0; ks < 8; ks++) {
            int kb = ks * 32 + kofs0;
            uint32_t a0 = *(const uint32_t*)(Ab + kb);
            uint32_t a1 = *(const uint32_t*)(Ab + 8 * BROW + kb);
            uint32_t a2 = *(const uint32_t*)(Ab + kb + 16);
            uint32_t a3 = *(const uint32_t*)(Ab + 8 * BROW + kb + 16);
#pragma unroll
            for (int nt = 0; nt < NT; nt++) {
                const char* Bp = Bb + (nt * 8 + g) * BROW + kb;
                uint32_t b0 = *(const uint32_t*)(Bp);
                uint32_t b1 = *(const uint32_t*)(Bp + 16);
                mma16816(acc + nt * 4, a0, a1, a2, a3, b0, b1);
            }
        }
    }

    int r0 = rowBase + wid * 16 + g, r1 = r0 + 8;
    float dv0 = (r0 < M) ? g_dinv[r0] : 0.f;
    float dv1 = (r1 < M) ? g_dinv[r1] : 0.f;
    float q0 = dv0 * dv0, q1 = dv1 * dv1;
#pragma unroll
    for (int nt = 0; nt < NT; nt++) {
        int c = nt * 8 + t4 * 2;
        float2 bv = *(const float2*)&bias_g[c];
        if (r0 < M) {
            float2 s = make_float2(acc[nt * 4 + 0] * dv0, acc[nt * 4 + 1] * dv0);
            *(float2*)&Ysc[(size_t)r0 * NOUT + c] = s;
            float2 a = make_float2(fmaf(acc[nt * 4 + 0], q0, bv.x),
                                   fmaf(acc[nt * 4 + 1], q0, bv.y));
            *(float2*)&Yagg[(size_t)r0 * NOUT + c] = a;
        }
        if (r1 < M) {
            float2 s = make_float2(acc[nt * 4 + 2] * dv1, acc[nt * 4 + 3] * dv1);
            *(float2*)&Ysc[(size_t)r1 * NOUT + c] = s;
            float2 a = make_float2(fmaf(acc[nt * 4 + 2], q1, bv.x),
                                   fmaf(acc[nt * 4 + 3], q1, bv.y));
            *(float2*)&Yagg[(size_t)r1 * NOUT + c] = a;
        }
    }
}

// ---------------- CSR gather: warp per dst row, register accumulation -------
// g_h[r] += dinv[r] * Σ_{src in-edges} g_xw[src]   (g_xw pre-scaled by dinv[src];
// g_h initialized by GEMM epilogue to selfloop+bias)
__global__ __launch_bounds__(256) void gather128_kernel(int M) {
    int r = (blockIdx.x * blockDim.x + threadIdx.x) >> 5;
    int lane = threadIdx.x & 31;
    if (r >= M) return;
    int start = g_row[r];
    int deg = g_deg[r];
    float4 acc = make_float4(0.f, 0.f, 0.f, 0.f);
    for (int j0 = 0; j0 < deg; j0 += 32) {
        int n = min(32, deg - j0);
        int s = (j0 + lane < deg) ? g_esrc[start + j0 + lane] : 0;
        for (int i = 0; i < n; i++) {
            int si = __shfl_sync(0xFFFFFFFFu, s, i);
            float4 v = *((const float4*)(g_xw + (size_t)si * 128) + lane);
            acc.x += v.x; acc.y += v.y; acc.z += v.z; acc.w += v.w;
        }
    }
    float w = g_dinv[r];
    float4* hp = (float4*)(g_h + (size_t)r * 128) + lane;
    float4 h = *hp;
    h.x = fmaf(acc.x, w, h.x); h.y = fmaf(acc.y, w, h.y);
    h.z = fmaf(acc.z, w, h.z); h.w = fmaf(acc.w, w, h.w);
    *hp = h;
}

__global__ __launch_bounds__(256) void gather40_kernel(float* __restrict__ out, int M) {
    int r = (blockIdx.x * blockDim.x + threadIdx.x) >> 5;
    int lane = threadIdx.x & 31;
    if (r >= M) return;
    int start = g_row[r];
    int deg = g_deg[r];
    float4 acc = make_float4(0.f, 0.f, 0.f, 0.f);
    for (int j0 = 0; j0 < deg; j0 += 32) {
        int n = min(32, deg - j0);
        int s = (j0 + lane < deg) ? g_esrc[start + j0 + lane] : 0;
        for (int i = 0; i < n; i++) {
            int si = __shfl_sync(0xFFFFFFFFu, s, i);
            if (lane < 10) {
                float4 v = *((const float4*)(g_hw + (size_t)si * 40) + lane);
                acc.x += v.x; acc.y += v.y; acc.z += v.z; acc.w += v.w;
            }
        }
    }
    if (lane < 10) {
        float w = g_dinv[r];
        float4* op = (float4*)(out + (size_t)r * 40) + lane;
        float4 h = *op;
        h.x = fmaf(acc.x, w, h.x); h.y = fmaf(acc.y, w, h.y);
        h.z = fmaf(acc.z, w, h.z); h.w = fmaf(acc.w, w, h.w);
        *op = h;
    }
}

// ---------------- log_softmax over 40 classes, warp per row, in place -------
__global__ __launch_bounds__(256) void logsoftmax_kernel(float* __restrict__ out, int M) {
    int r = (blockIdx.x * blockDim.x + threadIdx.x) >> 5;
    int lane = threadIdx.x & 31;
    if (r >= M) return;
    float* row = out + (size_t)r * 40;
    float a = row[lane];
    float b = (lane < 8) ? row[32 + lane] : -INFINITY;
    float m = fmaxf(a, b);
#pragma unroll
    for (int o = 16; o; o >>= 1) m = fmaxf(m, __shfl_xor_sync(0xFFFFFFFFu, m, o));
    float s = __expf(a - m) + ((lane < 8) ? __expf(b - m) : 0.f);
#pragma unroll
    for (int o = 16; o; o >>= 1) s += __shfl_xor_sync(0xFFFFFFFFu, s, o);
    float L = m + __logf(s);
    row[lane] = a - L;
    if (lane < 8) row[32 + lane] = b - L;
}

// ---------------- launch ----------------
extern "C" void kernel_launch(void* const* d_in, const int* in_sizes, int n_in,
                              void* d_out, int out_size) {
    const float* x  = (const float*)d_in[0];
    const void*  ei = d_in[1];
    const float* W1 = (const float*)d_in[2];
    const float* b1 = (const float*)d_in[3];
    const float* W2 = (const float*)d_in[4];
    const float* b2 = (const float*)d_in[5];
    float* out = (float*)d_out;

    int M = in_sizes[0] / F1;       // 100000
    int E = in_sizes[1] / 2;        // 640000

    constexpr int SM1 = 2 * (128 * BROW) + 2 * (128 * BROW);  // 139264
    constexpr int SM2 = 2 * (128 * BROW) + 2 * (40 * BROW);   //  91392
    cudaFuncSetAttribute(mma_gemm_kernel<128, 128, false, 1>,
                         cudaFuncAttributeMaxDynamicSharedMemorySize, SM1);
    cudaFuncSetAttribute(mma_gemm_kernel<40, 40, true, 2>,
                         cudaFuncAttributeMaxDynamicSharedMemorySize, SM2);

    int NB = (M + 255) / 256;
    detect_kernel<<<1, 256>>>(ei);
    zero_deg_kernel<<<NB, 256>>>(M);
    deg_kernel<<<(E + 255) / 256, 256>>>(ei, E);
    dinv_kernel<<<NB, 256>>>(M);
    // CSR build
    scan1_kernel<<<NB, 256>>>(M);
    scan2_kernel<<<1, 32>>>(NB);
    scan3_kernel<<<NB, 256>>>(M);
    reorder_kernel<<<(E + 255) / 256, 256>>>(ei, E);
    prep_w_kernel<<<64, 256>>>(W1, W2);

    int nCTA = (M + 127) / 128;
    // layer 1: g_xw = (x@W1)*dinv ; g_h = (x@W1)*dinv^2 + b1, then CSR gather
    mma_gemm_kernel<128, 128, false, 1><<<nCTA, 256, SM1>>>(x, b1, nullptr, M);
    gather128_kernel<<<(M * 32 + 255) / 256, 256>>>(M);

    // layer 2
    mma_gemm_kernel<40, 40, true, 2><<<nCTA, 256, SM2>>>(nullptr, b2, out, M);
    gather40_kernel<<<(M * 32 + 255) / 256, 256>>>(out, M);

    logsoftmax_kernel<<<(M * 32 + 255) / 256, 256>>>(out, M);
}